// round 12
// baseline (speedup 1.0000x reference)
#include <cuda_runtime.h>
#include <cuda_fp16.h>
#include <math.h>

#define NB   64
#define G    8
#define NT   512
#define TS   16
#define DIM  128
#define CLIP_LIM 256.0f

#define HROWS 16       // h rows per k3 block
#define PROWS 68       // padded sR rows: tap+2 in [0,68)
#define K1T   512      // k1 threads per block
#define K1W   (K1T/32) // k1 warps (hist copies)

__device__ float    g_cdf[NB * NT];           // [n][i][j][k]
__device__ float    g_P[DIM * NB * G * G];    // [d][n][j][k]
__device__ float    g_M[DIM * G];
__device__ unsigned g_minmax[2];

// ---------------------------------------------------------------- helpers
__device__ __forceinline__ float bspline5(float x) {
    float t = fabsf(x);
    float t2 = t * t, t3 = t2 * t, t4 = t2 * t2, t5 = t4 * t;
    if (t < 1.0f)
        return 11.0f/20.0f - 0.5f*t2 + 0.25f*t4 - t5*(1.0f/12.0f);
    if (t < 2.0f)
        return 17.0f/40.0f + t*(5.0f/8.0f) - t2*(7.0f/4.0f) + t3*(5.0f/4.0f)
             - t4*(3.0f/8.0f) + t5*(1.0f/24.0f);
    if (t < 3.0f) {
        float u = 3.0f - t;
        float u2 = u * u;
        return u2 * u2 * u * (1.0f/120.0f);
    }
    return 0.0f;
}

__device__ __forceinline__ int reflect_dct2(int i, int n) {
    int m = i % (2 * n);
    if (m < 0) m += 2 * n;
    return (m < n) ? m : (2 * n - 1 - m);
}

__device__ __forceinline__ unsigned fenc(float f) {
    unsigned u = __float_as_uint(f);
    return (u & 0x80000000u) ? ~u : (u | 0x80000000u);
}
__device__ __forceinline__ float fdec(unsigned e) {
    unsigned u = (e & 0x80000000u) ? (e & 0x7FFFFFFFu) : ~e;
    return __uint_as_float(u);
}

__device__ __forceinline__ float w1poly(float t) {
    return 17.0f/40.0f + t*(5.0f/8.0f + t*(-7.0f/4.0f + t*(5.0f/4.0f
         + t*(-3.0f/8.0f + t*(1.0f/24.0f)))));
}
__device__ __forceinline__ float w0poly(float t) {
    float t2 = t * t;
    float t4 = t2 * t2;
    return 11.0f/20.0f - 0.5f*t2 + 0.25f*t4 - t4*t*(1.0f/12.0f);
}

// ---------------------------------------------------------------- K1 (+ fused k0 matrix block)
__global__ void __launch_bounds__(K1T) k1_hist(const float* __restrict__ x) {
    int tid = threadIdx.x;

    if (blockIdx.x == NT) {          // fused k0: axis matrix
        int s = tid;
        if (s < DIM) {
            const float start = -0.53125f;
            const float step  = 8.0625f / 127.0f;
            float c = start + (float)s * step;
            float row[G];
            #pragma unroll
            for (int i = 0; i < G; i++) row[i] = 0.0f;
            int base = (int)floorf(c) - 2;
            #pragma unroll
            for (int t = 0; t < 6; t++) {
                int tap = base + t;
                float w = bspline5(c - (float)tap);
                row[reflect_dct2(tap, G)] += w;
            }
            #pragma unroll
            for (int i = 0; i < G; i++) g_M[s * G + i] = row[i];
        }
        return;
    }

    __shared__ float histw[K1W][NB];   // 4 KB
    int tile = blockIdx.x;
    int ti = tile >> 6, tj = (tile >> 3) & 7, tk = tile & 7;
    int warp = tid >> 5;

    for (int i = tid; i < K1W * NB; i += K1T) ((float*)histw)[i] = 0.0f;
    __syncthreads();

    int d0 = ti * TS, h0 = tj * TS, w0 = tk * TS;
    const float4* x4 = (const float4*)x;

    #pragma unroll
    for (int it = 0; it < 2; it++) {
        int f  = it * K1T + tid;      // 0..1023 float4 index within tile
        int w4 = f & 3;
        int rc = f >> 2;
        int a  = rc >> 4, b = rc & 15;
        float4 v = x4[((((d0 + a) * DIM) + (h0 + b)) * DIM + w0) / 4 + w4];

        float vv[4] = {v.x, v.y, v.z, v.w};
        #pragma unroll
        for (int q = 0; q < 4; q++) {
            float pos = vv[q] * 63.0f;
            int nb = __float2int_rn(pos);
            nb = min(63, max(0, nb));
            float diff = pos - (float)nb;
            if (fabsf(diff) < 0.27f) {
                float u = diff * (1000.0f / 63.0f);
                atomicAdd(&histw[warp][nb], __expf(-0.5f * u * u));
            }
        }
    }
    __syncthreads();

    // warp-parallel epilogue: lane l owns bins 2l, 2l+1
    if (tid < 32) {
        int l = tid;
        float a = 0.0f, b = 0.0f;
        #pragma unroll
        for (int w = 0; w < K1W; w++) { a += histw[w][2 * l]; b += histw[w][2 * l + 1]; }

        // histos[n] = raw[n] / (sum(raw)/4096 + 1e-10)
        float S = a + b;
        #pragma unroll
        for (int off = 16; off > 0; off >>= 1) S += __shfl_xor_sync(0xFFFFFFFFu, S, off);
        float inv = 1.0f / (S * (1.0f / 4096.0f) + 1e-10f);
        float ha = fminf(a * inv, CLIP_LIM);
        float hb = fminf(b * inv, CLIP_LIM);

        float T = ha + hb;
        #pragma unroll
        for (int off = 16; off > 0; off >>= 1) T += __shfl_xor_sync(0xFFFFFFFFu, T, off);
        float clipped  = 4096.0f - T;
        float residual = fmodf(clipped, 64.0f);
        float redist   = (clipped - residual) * (1.0f / 64.0f);

        float hva = ha + redist + (((float)(2 * l)     < residual) ? 1.0f : 0.0f);
        float hvb = hb + redist + (((float)(2 * l + 1) < residual) ? 1.0f : 0.0f);

        // inclusive scan over pair sums
        float ps = hva + hvb;
        float scan = ps;
        #pragma unroll
        for (int off = 1; off < 32; off <<= 1) {
            float t = __shfl_up_sync(0xFFFFFFFFu, scan, off);
            if (l >= off) scan += t;
        }
        float excl = scan - ps;
        int tbase = ti * 64 + tj * 8 + tk;
        const float sc = 63.0f / 4096.0f;
        g_cdf[(2 * l)     * NT + tbase] = (excl + hva) * sc;
        g_cdf[(2 * l + 1) * NT + tbase] = (excl + hva + hvb) * sc;
    }
}

// ---------------------------------------------------------------- K2 (+ minmax reset)
__global__ void k2_P() {
    int idx = blockIdx.x * blockDim.x + threadIdx.x;
    if (idx == 0) { g_minmax[0] = 0xFFFFFFFFu; g_minmax[1] = 0u; }
    int k = idx & 7;
    int j = (idx >> 3) & 7;
    int n = (idx >> 6) & 63;
    int d = idx >> 12;
    float acc = 0.0f;
    #pragma unroll
    for (int i = 0; i < 8; i++)
        acc += g_M[d * 8 + i] * g_cdf[n * NT + i * 64 + j * 8 + k];
    g_P[idx] = acc;
}

// ---------------------------------------------------------------- K3
// grid (8, 128). 16 h-rows/block; fp16 padded R rows; HFMA2 dot; 7 CTAs/SM
// (single wave: 1024 blocks <= 148*7).
__global__ void __launch_bounds__(256, 7) k3_final(const float* __restrict__ x,
                                                   float* __restrict__ out) {
    __shared__ __align__(16) __half sR[HROWS * PROWS * 8];  // 17408 B
    __shared__ __align__(16) float sMh[HROWS * G];          // 512 B

    int d   = blockIdx.y;
    int hb  = blockIdx.x * HROWS;
    int tid = threadIdx.x;
    int hsub = tid >> 7;
    int w    = tid & 127;

    if (tid < HROWS * G) sMh[tid] = g_M[hb * G + tid];

    // P slice direct global->regs: P[d][bn][j][bq*2 .. bq*2+1]
    int bn = tid >> 2;          // 0..63
    int bq = tid & 3;           // 0..3
    float2 p[8];
    #pragma unroll
    for (int j = 0; j < 8; j++)
        p[j] = *(const float2*)&g_P[((d * NB + bn) * G + j) * G + bq * 2];

    // per-thread w weights as half2 (for HFMA2 dot)
    __half2 mh[4];
    {
        const float* m = &g_M[w * G];
        mh[0] = __float22half2_rn(make_float2(m[0], m[1]));
        mh[1] = __float22half2_rn(make_float2(m[2], m[3]));
        mh[2] = __float22half2_rn(make_float2(m[4], m[5]));
        mh[3] = __float22half2_rn(make_float2(m[6], m[7]));
    }
    __syncthreads();   // sMh ready

    // mirror duplicate slot (padded reflection): bn 1->0, 0->1, 62->67, 63->66
    bool hasdup = (bn < 2) | (bn >= 62);
    int dupoff  = ((bn < 2) ? (1 - bn) : (129 - bn)) * 4 + bq;

    // build all 16 R rows; one predicated mirror store
    __half2* sR2 = (__half2*)sR;
    #pragma unroll
    for (int r = 0; r < HROWS; r++) {
        float4 m01 = *(const float4*)&sMh[r * 8];
        float4 m23 = *(const float4*)&sMh[r * 8 + 4];
        float2 a = make_float2(0.f, 0.f);
        a.x = fmaf(m01.x, p[0].x, a.x);  a.y = fmaf(m01.x, p[0].y, a.y);
        a.x = fmaf(m01.y, p[1].x, a.x);  a.y = fmaf(m01.y, p[1].y, a.y);
        a.x = fmaf(m01.z, p[2].x, a.x);  a.y = fmaf(m01.z, p[2].y, a.y);
        a.x = fmaf(m01.w, p[3].x, a.x);  a.y = fmaf(m01.w, p[3].y, a.y);
        a.x = fmaf(m23.x, p[4].x, a.x);  a.y = fmaf(m23.x, p[4].y, a.y);
        a.x = fmaf(m23.y, p[5].x, a.x);  a.y = fmaf(m23.y, p[5].y, a.y);
        a.x = fmaf(m23.z, p[6].x, a.x);  a.y = fmaf(m23.z, p[6].y, a.y);
        a.x = fmaf(m23.w, p[7].x, a.x);  a.y = fmaf(m23.w, p[7].y, a.y);
        __half2 h = __float22half2_rn(a);
        int rb = r * PROWS * 4;
        sR2[rb + (bn + 2) * 4 + bq] = h;
        if (hasdup) sR2[rb + dupoff] = h;
    }
    __syncthreads();   // the ONLY barrier before the voxel loop

    float vmin =  3.0e38f, vmax = -3.0e38f;

    const float* xrow = x + (d * DIM + hb + hsub) * DIM + w;
    float vcur = xrow[0];

    #pragma unroll
    for (int i = 0; i < 8; i++) {
        int r = 2 * i + hsub;
        float vnext = 0.0f;
        if (i < 7) vnext = xrow[(2 * i + 2) * DIM];

        float cb = vcur * 63.0f;
        float fb = floorf(cb);
        int t2   = (int)fb;          // padded row of first tap
        float f  = cb - fb;
        float g1 = 1.0f - f;

        float f5g = f * f; f5g = f5g * f5g * f;
        float g5g = g1 * g1; g5g = g5g * g5g * g1;
        float wb[6];
        wb[0] = g5g * (1.0f / 120.0f);
        wb[1] = w1poly(1.0f + f);
        wb[2] = w0poly(f);
        wb[3] = w0poly(g1);
        wb[4] = w1poly(2.0f - f);
        wb[5] = f5g * (1.0f / 120.0f);

        const uint4* Rr = (const uint4*)(sR + r * PROWS * 8) + t2;
        float acc = 0.0f;
        #pragma unroll
        for (int t = 0; t < 6; t++) {
            uint4 u = Rr[t];                       // one LDS.128: 8 halves
            __half2 h0 = *reinterpret_cast<__half2*>(&u.x);
            __half2 h1 = *reinterpret_cast<__half2*>(&u.y);
            __half2 h2 = *reinterpret_cast<__half2*>(&u.z);
            __half2 h3 = *reinterpret_cast<__half2*>(&u.w);
            __half2 a2 = __hmul2(mh[0], h0);
            a2 = __hfma2(mh[1], h1, a2);
            a2 = __hfma2(mh[2], h2, a2);
            a2 = __hfma2(mh[3], h3, a2);
            float2 fa = __half22float2(a2);
            acc = fmaf(wb[t], fa.x + fa.y, acc);
        }
        out[(d * DIM + hb + r) * DIM + w] = acc;
        vmin = fminf(vmin, acc);
        vmax = fmaxf(vmax, acc);
        vcur = vnext;
    }

    #pragma unroll
    for (int off = 16; off > 0; off >>= 1) {
        vmin = fminf(vmin, __shfl_xor_sync(0xFFFFFFFFu, vmin, off));
        vmax = fmaxf(vmax, __shfl_xor_sync(0xFFFFFFFFu, vmax, off));
    }
    if ((tid & 31) == 0) {
        atomicMin(&g_minmax[0], fenc(vmin));
        atomicMax(&g_minmax[1], fenc(vmax));
    }
}

// ---------------------------------------------------------------- K4: 2 float4/thread, loads batched, 1024 blocks
__global__ void k4_norm(float4* __restrict__ out, int n4) {
    int i0 = blockIdx.x * 512 + threadIdx.x;
    float mn = fdec(g_minmax[0]);
    float mx = fdec(g_minmax[1]);
    float inv = 1.0f / (mx - mn + 1e-10f);
    float4 v0 = out[i0];
    float4 v1 = out[i0 + 256];
    float4 r0, r1;
    r0.x = (v0.x - mn) * inv; r0.y = (v0.y - mn) * inv;
    r0.z = (v0.z - mn) * inv; r0.w = (v0.w - mn) * inv;
    r1.x = (v1.x - mn) * inv; r1.y = (v1.y - mn) * inv;
    r1.z = (v1.z - mn) * inv; r1.w = (v1.w - mn) * inv;
    out[i0] = r0;
    out[i0 + 256] = r1;
}

// ---------------------------------------------------------------- launch
extern "C" void kernel_launch(void* const* d_in, const int* in_sizes, int n_in,
                              void* d_out, int out_size) {
    const float* x = (const float*)d_in[0];
    float* out = (float*)d_out;

    k1_hist<<<NT + 1, K1T>>>(x);
    k2_P<<<(DIM * NB * G * G) / 256, 256>>>();
    k3_final<<<dim3(DIM / HROWS, DIM), 256>>>(x, out);
    int n4 = out_size / 4;                 // 524288 float4 = 1024 blocks * 512
    k4_norm<<<n4 / 512, 256>>>((float4*)out, n4);
}

// round 13
// speedup vs baseline: 1.1588x; 1.1588x over previous
#include <cuda_runtime.h>
#include <cuda_fp16.h>
#include <math.h>

#define NB   64
#define G    8
#define NT   512
#define TS   16
#define DIM  128
#define CLIP_LIM 256.0f

#define HROWS 16       // h rows per k3 block
#define PROWS 68       // padded sR rows: tap+2 in [0,68)
#define K1T   512      // k1 threads per block
#define K1W   (K1T/32) // k1 warps (hist copies)

__device__ float    g_cdf[NB * NT];           // [n][i][j][k]
__device__ float    g_P[DIM * NB * G * G];    // [d][n][j][k]
__device__ float    g_M[DIM * G];
__device__ unsigned g_minmax[2];

// ---------------------------------------------------------------- helpers
__device__ __forceinline__ float bspline5(float x) {
    float t = fabsf(x);
    float t2 = t * t, t3 = t2 * t, t4 = t2 * t2, t5 = t4 * t;
    if (t < 1.0f)
        return 11.0f/20.0f - 0.5f*t2 + 0.25f*t4 - t5*(1.0f/12.0f);
    if (t < 2.0f)
        return 17.0f/40.0f + t*(5.0f/8.0f) - t2*(7.0f/4.0f) + t3*(5.0f/4.0f)
             - t4*(3.0f/8.0f) + t5*(1.0f/24.0f);
    if (t < 3.0f) {
        float u = 3.0f - t;
        float u2 = u * u;
        return u2 * u2 * u * (1.0f/120.0f);
    }
    return 0.0f;
}

__device__ __forceinline__ int reflect_dct2(int i, int n) {
    int m = i % (2 * n);
    if (m < 0) m += 2 * n;
    return (m < n) ? m : (2 * n - 1 - m);
}

__device__ __forceinline__ unsigned fenc(float f) {
    unsigned u = __float_as_uint(f);
    return (u & 0x80000000u) ? ~u : (u | 0x80000000u);
}
__device__ __forceinline__ float fdec(unsigned e) {
    unsigned u = (e & 0x80000000u) ? (e & 0x7FFFFFFFu) : ~e;
    return __uint_as_float(u);
}

__device__ __forceinline__ float w1poly(float t) {
    return 17.0f/40.0f + t*(5.0f/8.0f + t*(-7.0f/4.0f + t*(5.0f/4.0f
         + t*(-3.0f/8.0f + t*(1.0f/24.0f)))));
}
__device__ __forceinline__ float w0poly(float t) {
    float t2 = t * t;
    float t4 = t2 * t2;
    return 11.0f/20.0f - 0.5f*t2 + 0.25f*t4 - t4*t*(1.0f/12.0f);
}

// ---------------------------------------------------------------- K1 (+ fused k0 matrix block)
__global__ void __launch_bounds__(K1T) k1_hist(const float* __restrict__ x) {
    int tid = threadIdx.x;

    if (blockIdx.x == NT) {          // fused k0: axis matrix
        int s = tid;
        if (s < DIM) {
            const float start = -0.53125f;
            const float step  = 8.0625f / 127.0f;
            float c = start + (float)s * step;
            float row[G];
            #pragma unroll
            for (int i = 0; i < G; i++) row[i] = 0.0f;
            int base = (int)floorf(c) - 2;
            #pragma unroll
            for (int t = 0; t < 6; t++) {
                int tap = base + t;
                float w = bspline5(c - (float)tap);
                row[reflect_dct2(tap, G)] += w;
            }
            #pragma unroll
            for (int i = 0; i < G; i++) g_M[s * G + i] = row[i];
        }
        return;
    }

    __shared__ float histw[K1W][NB];   // 4 KB
    int tile = blockIdx.x;
    int ti = tile >> 6, tj = (tile >> 3) & 7, tk = tile & 7;
    int warp = tid >> 5;

    for (int i = tid; i < K1W * NB; i += K1T) ((float*)histw)[i] = 0.0f;
    __syncthreads();

    int d0 = ti * TS, h0 = tj * TS, w0 = tk * TS;
    const float4* x4 = (const float4*)x;

    #pragma unroll
    for (int it = 0; it < 2; it++) {
        int f  = it * K1T + tid;      // 0..1023 float4 index within tile
        int w4 = f & 3;
        int rc = f >> 2;
        int a  = rc >> 4, b = rc & 15;
        float4 v = x4[((((d0 + a) * DIM) + (h0 + b)) * DIM + w0) / 4 + w4];

        float vv[4] = {v.x, v.y, v.z, v.w};
        #pragma unroll
        for (int q = 0; q < 4; q++) {
            float pos = vv[q] * 63.0f;
            int nb = __float2int_rn(pos);
            nb = min(63, max(0, nb));
            float diff = pos - (float)nb;
            if (fabsf(diff) < 0.27f) {
                float u = diff * (1000.0f / 63.0f);
                atomicAdd(&histw[warp][nb], __expf(-0.5f * u * u));
            }
        }
    }
    __syncthreads();

    // warp-parallel epilogue: lane l owns bins 2l, 2l+1
    if (tid < 32) {
        int l = tid;
        float a = 0.0f, b = 0.0f;
        #pragma unroll
        for (int w = 0; w < K1W; w++) { a += histw[w][2 * l]; b += histw[w][2 * l + 1]; }

        // histos[n] = raw[n] / (sum(raw)/4096 + 1e-10)
        float S = a + b;
        #pragma unroll
        for (int off = 16; off > 0; off >>= 1) S += __shfl_xor_sync(0xFFFFFFFFu, S, off);
        float inv = 1.0f / (S * (1.0f / 4096.0f) + 1e-10f);
        float ha = fminf(a * inv, CLIP_LIM);
        float hb = fminf(b * inv, CLIP_LIM);

        float T = ha + hb;
        #pragma unroll
        for (int off = 16; off > 0; off >>= 1) T += __shfl_xor_sync(0xFFFFFFFFu, T, off);
        float clipped  = 4096.0f - T;
        float residual = fmodf(clipped, 64.0f);
        float redist   = (clipped - residual) * (1.0f / 64.0f);

        float hva = ha + redist + (((float)(2 * l)     < residual) ? 1.0f : 0.0f);
        float hvb = hb + redist + (((float)(2 * l + 1) < residual) ? 1.0f : 0.0f);

        // inclusive scan over pair sums
        float ps = hva + hvb;
        float scan = ps;
        #pragma unroll
        for (int off = 1; off < 32; off <<= 1) {
            float t = __shfl_up_sync(0xFFFFFFFFu, scan, off);
            if (l >= off) scan += t;
        }
        float excl = scan - ps;
        int tbase = ti * 64 + tj * 8 + tk;
        const float sc = 63.0f / 4096.0f;
        g_cdf[(2 * l)     * NT + tbase] = (excl + hva) * sc;
        g_cdf[(2 * l + 1) * NT + tbase] = (excl + hva + hvb) * sc;
    }
}

// ---------------------------------------------------------------- K2 (+ minmax reset)
__global__ void k2_P() {
    int idx = blockIdx.x * blockDim.x + threadIdx.x;
    if (idx == 0) { g_minmax[0] = 0xFFFFFFFFu; g_minmax[1] = 0u; }
    int k = idx & 7;
    int j = (idx >> 3) & 7;
    int n = (idx >> 6) & 63;
    int d = idx >> 12;
    float acc = 0.0f;
    #pragma unroll
    for (int i = 0; i < 8; i++)
        acc += g_M[d * 8 + i] * g_cdf[n * NT + i * 64 + j * 8 + k];
    g_P[idx] = acc;
}

// ---------------------------------------------------------------- K3
// grid (8, 128). 16 h-rows/block; fp16 padded R rows; HFMA2 dot; 6 CTAs/SM.
// 4-tap folded bin spline: outer taps (weight <= 1/120) folded into neighbors.
__global__ void __launch_bounds__(256, 6) k3_final(const float* __restrict__ x,
                                                   float* __restrict__ out) {
    __shared__ __align__(16) __half sR[HROWS * PROWS * 8];  // 17408 B
    __shared__ __align__(16) float sMh[HROWS * G];          // 512 B

    int d   = blockIdx.y;
    int hb  = blockIdx.x * HROWS;
    int tid = threadIdx.x;
    int hsub = tid >> 7;
    int w    = tid & 127;

    if (tid < HROWS * G) sMh[tid] = g_M[hb * G + tid];

    // P slice direct global->regs: P[d][bn][j][bq*2 .. bq*2+1]
    int bn = tid >> 2;          // 0..63
    int bq = tid & 3;           // 0..3
    float2 p[8];
    #pragma unroll
    for (int j = 0; j < 8; j++)
        p[j] = *(const float2*)&g_P[((d * NB + bn) * G + j) * G + bq * 2];

    // per-thread w weights as half2 (for HFMA2 dot)
    __half2 mh[4];
    {
        const float* m = &g_M[w * G];
        mh[0] = __float22half2_rn(make_float2(m[0], m[1]));
        mh[1] = __float22half2_rn(make_float2(m[2], m[3]));
        mh[2] = __float22half2_rn(make_float2(m[4], m[5]));
        mh[3] = __float22half2_rn(make_float2(m[6], m[7]));
    }
    __syncthreads();   // sMh ready

    // mirror duplicate slot (padded reflection): bn 1->0, 0->1, 62->67, 63->66
    bool hasdup = (bn < 2) | (bn >= 62);
    int dupoff  = ((bn < 2) ? (1 - bn) : (129 - bn)) * 4 + bq;

    // build all 16 R rows; one predicated mirror store
    __half2* sR2 = (__half2*)sR;
    #pragma unroll
    for (int r = 0; r < HROWS; r++) {
        float4 m01 = *(const float4*)&sMh[r * 8];
        float4 m23 = *(const float4*)&sMh[r * 8 + 4];
        float2 a = make_float2(0.f, 0.f);
        a.x = fmaf(m01.x, p[0].x, a.x);  a.y = fmaf(m01.x, p[0].y, a.y);
        a.x = fmaf(m01.y, p[1].x, a.x);  a.y = fmaf(m01.y, p[1].y, a.y);
        a.x = fmaf(m01.z, p[2].x, a.x);  a.y = fmaf(m01.z, p[2].y, a.y);
        a.x = fmaf(m01.w, p[3].x, a.x);  a.y = fmaf(m01.w, p[3].y, a.y);
        a.x = fmaf(m23.x, p[4].x, a.x);  a.y = fmaf(m23.x, p[4].y, a.y);
        a.x = fmaf(m23.y, p[5].x, a.x);  a.y = fmaf(m23.y, p[5].y, a.y);
        a.x = fmaf(m23.z, p[6].x, a.x);  a.y = fmaf(m23.z, p[6].y, a.y);
        a.x = fmaf(m23.w, p[7].x, a.x);  a.y = fmaf(m23.w, p[7].y, a.y);
        __half2 h = __float22half2_rn(a);
        int rb = r * PROWS * 4;
        sR2[rb + (bn + 2) * 4 + bq] = h;
        if (hasdup) sR2[rb + dupoff] = h;
    }
    __syncthreads();   // the ONLY barrier before the voxel loop

    float vmin =  3.0e38f, vmax = -3.0e38f;

    const float* xrow = x + (d * DIM + hb + hsub) * DIM + w;
    float vcur = xrow[0];

    #pragma unroll
    for (int i = 0; i < 8; i++) {
        int r = 2 * i + hsub;
        float vnext = 0.0f;
        if (i < 7) vnext = xrow[(2 * i + 2) * DIM];

        float cb = vcur * 63.0f;
        float fb = floorf(cb);
        int t2   = (int)fb;          // padded row of first (dropped) tap
        float f  = cb - fb;
        float g1 = 1.0f - f;

        float f5g = f * f; f5g = f5g * f5g * f;
        float g5g = g1 * g1; g5g = g5g * g5g * g1;
        // 4-tap folded weights: outer taps folded into their neighbors
        float wb[4];
        wb[0] = w1poly(1.0f + f) + g5g * (1.0f / 120.0f);
        wb[1] = w0poly(f);
        wb[2] = w0poly(g1);
        wb[3] = w1poly(2.0f - f) + f5g * (1.0f / 120.0f);

        const uint4* Rr = (const uint4*)(sR + r * PROWS * 8) + (t2 + 1);
        float acc = 0.0f;
        #pragma unroll
        for (int t = 0; t < 4; t++) {
            uint4 u = Rr[t];                       // one LDS.128: 8 halves
            __half2 h0 = *reinterpret_cast<__half2*>(&u.x);
            __half2 h1 = *reinterpret_cast<__half2*>(&u.y);
            __half2 h2 = *reinterpret_cast<__half2*>(&u.z);
            __half2 h3 = *reinterpret_cast<__half2*>(&u.w);
            __half2 a2 = __hmul2(mh[0], h0);
            a2 = __hfma2(mh[1], h1, a2);
            a2 = __hfma2(mh[2], h2, a2);
            a2 = __hfma2(mh[3], h3, a2);
            float2 fa = __half22float2(a2);
            acc = fmaf(wb[t], fa.x + fa.y, acc);
        }
        out[(d * DIM + hb + r) * DIM + w] = acc;
        vmin = fminf(vmin, acc);
        vmax = fmaxf(vmax, acc);
        vcur = vnext;
    }

    #pragma unroll
    for (int off = 16; off > 0; off >>= 1) {
        vmin = fminf(vmin, __shfl_xor_sync(0xFFFFFFFFu, vmin, off));
        vmax = fmaxf(vmax, __shfl_xor_sync(0xFFFFFFFFu, vmax, off));
    }
    if ((tid & 31) == 0) {
        atomicMin(&g_minmax[0], fenc(vmin));
        atomicMax(&g_minmax[1], fenc(vmax));
    }
}

// ---------------------------------------------------------------- K4: 2 float4/thread, loads batched, 1024 blocks
__global__ void k4_norm(float4* __restrict__ out, int n4) {
    int i0 = blockIdx.x * 512 + threadIdx.x;
    float mn = fdec(g_minmax[0]);
    float mx = fdec(g_minmax[1]);
    float inv = 1.0f / (mx - mn + 1e-10f);
    float4 v0 = out[i0];
    float4 v1 = out[i0 + 256];
    float4 r0, r1;
    r0.x = (v0.x - mn) * inv; r0.y = (v0.y - mn) * inv;
    r0.z = (v0.z - mn) * inv; r0.w = (v0.w - mn) * inv;
    r1.x = (v1.x - mn) * inv; r1.y = (v1.y - mn) * inv;
    r1.z = (v1.z - mn) * inv; r1.w = (v1.w - mn) * inv;
    out[i0] = r0;
    out[i0 + 256] = r1;
}

// ---------------------------------------------------------------- launch
extern "C" void kernel_launch(void* const* d_in, const int* in_sizes, int n_in,
                              void* d_out, int out_size) {
    const float* x = (const float*)d_in[0];
    float* out = (float*)d_out;

    k1_hist<<<NT + 1, K1T>>>(x);
    k2_P<<<(DIM * NB * G * G) / 256, 256>>>();
    k3_final<<<dim3(DIM / HROWS, DIM), 256>>>(x, out);
    int n4 = out_size / 4;                 // 524288 float4 = 1024 blocks * 512
    k4_norm<<<n4 / 512, 256>>>((float4*)out, n4);
}

// round 14
// speedup vs baseline: 1.1648x; 1.0052x over previous
#include <cuda_runtime.h>
#include <cuda_fp16.h>
#include <math.h>

#define NB   64
#define G    8
#define NT   512
#define TS   16
#define DIM  128
#define CLIP_LIM 256.0f

#define HROWS 32       // h rows per k3 block
#define PROWS 68       // padded sR rows: tap+2 in [0,68)
#define K3BLOCKS ((DIM / HROWS) * DIM)   // 512 — must be <= resident capacity
#define K1T   512      // k1 threads per block
#define K1W   (K1T/32) // k1 warps (hist copies)

__device__ float    g_cdf[NB * NT];           // [n][i][j][k]
__device__ float    g_P[DIM * NB * G * G];    // [d][n][j][k]
__device__ float    g_M[DIM * G];
__device__ unsigned g_minmax[2];
__device__ unsigned g_barrier;

// ---------------------------------------------------------------- helpers
__device__ __forceinline__ float bspline5(float x) {
    float t = fabsf(x);
    float t2 = t * t, t3 = t2 * t, t4 = t2 * t2, t5 = t4 * t;
    if (t < 1.0f)
        return 11.0f/20.0f - 0.5f*t2 + 0.25f*t4 - t5*(1.0f/12.0f);
    if (t < 2.0f)
        return 17.0f/40.0f + t*(5.0f/8.0f) - t2*(7.0f/4.0f) + t3*(5.0f/4.0f)
             - t4*(3.0f/8.0f) + t5*(1.0f/24.0f);
    if (t < 3.0f) {
        float u = 3.0f - t;
        float u2 = u * u;
        return u2 * u2 * u * (1.0f/120.0f);
    }
    return 0.0f;
}

__device__ __forceinline__ int reflect_dct2(int i, int n) {
    int m = i % (2 * n);
    if (m < 0) m += 2 * n;
    return (m < n) ? m : (2 * n - 1 - m);
}

__device__ __forceinline__ unsigned fenc(float f) {
    unsigned u = __float_as_uint(f);
    return (u & 0x80000000u) ? ~u : (u | 0x80000000u);
}
__device__ __forceinline__ float fdec(unsigned e) {
    unsigned u = (e & 0x80000000u) ? (e & 0x7FFFFFFFu) : ~e;
    return __uint_as_float(u);
}

__device__ __forceinline__ float w1poly(float t) {
    return 17.0f/40.0f + t*(5.0f/8.0f + t*(-7.0f/4.0f + t*(5.0f/4.0f
         + t*(-3.0f/8.0f + t*(1.0f/24.0f)))));
}
__device__ __forceinline__ float w0poly(float t) {
    float t2 = t * t;
    float t4 = t2 * t2;
    return 11.0f/20.0f - 0.5f*t2 + 0.25f*t4 - t4*t*(1.0f/12.0f);
}

// ---------------------------------------------------------------- K1 (+ fused k0 matrix block)
__global__ void __launch_bounds__(K1T) k1_hist(const float* __restrict__ x) {
    int tid = threadIdx.x;

    if (blockIdx.x == NT) {          // fused k0: axis matrix
        int s = tid;
        if (s < DIM) {
            const float start = -0.53125f;
            const float step  = 8.0625f / 127.0f;
            float c = start + (float)s * step;
            float row[G];
            #pragma unroll
            for (int i = 0; i < G; i++) row[i] = 0.0f;
            int base = (int)floorf(c) - 2;
            #pragma unroll
            for (int t = 0; t < 6; t++) {
                int tap = base + t;
                float w = bspline5(c - (float)tap);
                row[reflect_dct2(tap, G)] += w;
            }
            #pragma unroll
            for (int i = 0; i < G; i++) g_M[s * G + i] = row[i];
        }
        return;
    }

    __shared__ float histw[K1W][NB];   // 4 KB
    int tile = blockIdx.x;
    int ti = tile >> 6, tj = (tile >> 3) & 7, tk = tile & 7;
    int warp = tid >> 5;

    for (int i = tid; i < K1W * NB; i += K1T) ((float*)histw)[i] = 0.0f;
    __syncthreads();

    int d0 = ti * TS, h0 = tj * TS, w0 = tk * TS;
    const float4* x4 = (const float4*)x;

    #pragma unroll
    for (int it = 0; it < 2; it++) {
        int f  = it * K1T + tid;      // 0..1023 float4 index within tile
        int w4 = f & 3;
        int rc = f >> 2;
        int a  = rc >> 4, b = rc & 15;
        float4 v = x4[((((d0 + a) * DIM) + (h0 + b)) * DIM + w0) / 4 + w4];

        float vv[4] = {v.x, v.y, v.z, v.w};
        #pragma unroll
        for (int q = 0; q < 4; q++) {
            float pos = vv[q] * 63.0f;
            int nb = __float2int_rn(pos);
            nb = min(63, max(0, nb));
            float diff = pos - (float)nb;
            if (fabsf(diff) < 0.27f) {
                float u = diff * (1000.0f / 63.0f);
                atomicAdd(&histw[warp][nb], __expf(-0.5f * u * u));
            }
        }
    }
    __syncthreads();

    // warp-parallel epilogue: lane l owns bins 2l, 2l+1
    if (tid < 32) {
        int l = tid;
        float a = 0.0f, b = 0.0f;
        #pragma unroll
        for (int w = 0; w < K1W; w++) { a += histw[w][2 * l]; b += histw[w][2 * l + 1]; }

        // histos[n] = raw[n] / (sum(raw)/4096 + 1e-10)
        float S = a + b;
        #pragma unroll
        for (int off = 16; off > 0; off >>= 1) S += __shfl_xor_sync(0xFFFFFFFFu, S, off);
        float inv = 1.0f / (S * (1.0f / 4096.0f) + 1e-10f);
        float ha = fminf(a * inv, CLIP_LIM);
        float hb = fminf(b * inv, CLIP_LIM);

        float T = ha + hb;
        #pragma unroll
        for (int off = 16; off > 0; off >>= 1) T += __shfl_xor_sync(0xFFFFFFFFu, T, off);
        float clipped  = 4096.0f - T;
        float residual = fmodf(clipped, 64.0f);
        float redist   = (clipped - residual) * (1.0f / 64.0f);

        float hva = ha + redist + (((float)(2 * l)     < residual) ? 1.0f : 0.0f);
        float hvb = hb + redist + (((float)(2 * l + 1) < residual) ? 1.0f : 0.0f);

        // inclusive scan over pair sums
        float ps = hva + hvb;
        float scan = ps;
        #pragma unroll
        for (int off = 1; off < 32; off <<= 1) {
            float t = __shfl_up_sync(0xFFFFFFFFu, scan, off);
            if (l >= off) scan += t;
        }
        float excl = scan - ps;
        int tbase = ti * 64 + tj * 8 + tk;
        const float sc = 63.0f / 4096.0f;
        g_cdf[(2 * l)     * NT + tbase] = (excl + hva) * sc;
        g_cdf[(2 * l + 1) * NT + tbase] = (excl + hva + hvb) * sc;
    }
}

// ---------------------------------------------------------------- K2 (+ minmax & barrier reset)
__global__ void k2_P() {
    int idx = blockIdx.x * blockDim.x + threadIdx.x;
    if (idx == 0) {
        g_minmax[0] = 0xFFFFFFFFu;
        g_minmax[1] = 0u;
        g_barrier   = 0u;
    }
    int k = idx & 7;
    int j = (idx >> 3) & 7;
    int n = (idx >> 6) & 63;
    int d = idx >> 12;
    float acc = 0.0f;
    #pragma unroll
    for (int i = 0; i < 8; i++)
        acc += g_M[d * 8 + i] * g_cdf[n * NT + i * 64 + j * 8 + k];
    g_P[idx] = acc;
}

// ---------------------------------------------------------------- K3 (+ fused normalization)
// grid (4, 128) = 512 blocks; 32 h-rows/block; fp16 padded R rows; HFMA2 dot;
// 4-tap folded bin spline; 6 CTAs/SM -> all 512 blocks co-resident, so a
// software grid barrier is deadlock-free; after it each block rescales its
// own out slice (replaces the k4 kernel).
__global__ void __launch_bounds__(256, 6) k3_final(const float* __restrict__ x,
                                                   float* __restrict__ out) {
    __shared__ __align__(16) __half sR[HROWS * PROWS * 8];  // 34816 B
    __shared__ __align__(16) float sMh[HROWS * G];          // 1 KB

    int d   = blockIdx.y;
    int hb  = blockIdx.x * HROWS;
    int tid = threadIdx.x;
    int hsub = tid >> 7;
    int w    = tid & 127;

    if (tid < HROWS * G) sMh[tid] = g_M[hb * G + tid];

    // P slice direct global->regs: P[d][bn][j][bq*2 .. bq*2+1]
    int bn = tid >> 2;          // 0..63
    int bq = tid & 3;           // 0..3
    float2 p[8];
    #pragma unroll
    for (int j = 0; j < 8; j++)
        p[j] = *(const float2*)&g_P[((d * NB + bn) * G + j) * G + bq * 2];

    // per-thread w weights as half2 (for HFMA2 dot)
    __half2 mh[4];
    {
        const float* m = &g_M[w * G];
        mh[0] = __float22half2_rn(make_float2(m[0], m[1]));
        mh[1] = __float22half2_rn(make_float2(m[2], m[3]));
        mh[2] = __float22half2_rn(make_float2(m[4], m[5]));
        mh[3] = __float22half2_rn(make_float2(m[6], m[7]));
    }
    __syncthreads();   // sMh ready

    // mirror duplicate slot (padded reflection): bn 1->0, 0->1, 62->67, 63->66
    bool hasdup = (bn < 2) | (bn >= 62);
    int dupoff  = ((bn < 2) ? (1 - bn) : (129 - bn)) * 4 + bq;

    // build all 32 R rows; one predicated mirror store
    __half2* sR2 = (__half2*)sR;
    #pragma unroll
    for (int r = 0; r < HROWS; r++) {
        float4 m01 = *(const float4*)&sMh[r * 8];
        float4 m23 = *(const float4*)&sMh[r * 8 + 4];
        float2 a = make_float2(0.f, 0.f);
        a.x = fmaf(m01.x, p[0].x, a.x);  a.y = fmaf(m01.x, p[0].y, a.y);
        a.x = fmaf(m01.y, p[1].x, a.x);  a.y = fmaf(m01.y, p[1].y, a.y);
        a.x = fmaf(m01.z, p[2].x, a.x);  a.y = fmaf(m01.z, p[2].y, a.y);
        a.x = fmaf(m01.w, p[3].x, a.x);  a.y = fmaf(m01.w, p[3].y, a.y);
        a.x = fmaf(m23.x, p[4].x, a.x);  a.y = fmaf(m23.x, p[4].y, a.y);
        a.x = fmaf(m23.y, p[5].x, a.x);  a.y = fmaf(m23.y, p[5].y, a.y);
        a.x = fmaf(m23.z, p[6].x, a.x);  a.y = fmaf(m23.z, p[6].y, a.y);
        a.x = fmaf(m23.w, p[7].x, a.x);  a.y = fmaf(m23.w, p[7].y, a.y);
        __half2 h = __float22half2_rn(a);
        int rb = r * PROWS * 4;
        sR2[rb + (bn + 2) * 4 + bq] = h;
        if (hasdup) sR2[rb + dupoff] = h;
    }
    __syncthreads();   // barrier before the voxel loop

    float vmin =  3.0e38f, vmax = -3.0e38f;

    const float* xrow = x + (d * DIM + hb + hsub) * DIM + w;
    float vcur = xrow[0];

    #pragma unroll
    for (int i = 0; i < HROWS / 2; i++) {
        int r = 2 * i + hsub;
        float vnext = 0.0f;
        if (i < HROWS / 2 - 1) vnext = xrow[(2 * i + 2) * DIM];

        float cb = vcur * 63.0f;
        float fb = floorf(cb);
        int t2   = (int)fb;          // padded row of first (dropped) tap
        float f  = cb - fb;
        float g1 = 1.0f - f;

        float f5g = f * f; f5g = f5g * f5g * f;
        float g5g = g1 * g1; g5g = g5g * g5g * g1;
        // 4-tap folded weights: outer taps folded into their neighbors
        float wb[4];
        wb[0] = w1poly(1.0f + f) + g5g * (1.0f / 120.0f);
        wb[1] = w0poly(f);
        wb[2] = w0poly(g1);
        wb[3] = w1poly(2.0f - f) + f5g * (1.0f / 120.0f);

        const uint4* Rr = (const uint4*)(sR + r * PROWS * 8) + (t2 + 1);
        float acc = 0.0f;
        #pragma unroll
        for (int t = 0; t < 4; t++) {
            uint4 u = Rr[t];                       // one LDS.128: 8 halves
            __half2 h0 = *reinterpret_cast<__half2*>(&u.x);
            __half2 h1 = *reinterpret_cast<__half2*>(&u.y);
            __half2 h2 = *reinterpret_cast<__half2*>(&u.z);
            __half2 h3 = *reinterpret_cast<__half2*>(&u.w);
            __half2 a2 = __hmul2(mh[0], h0);
            a2 = __hfma2(mh[1], h1, a2);
            a2 = __hfma2(mh[2], h2, a2);
            a2 = __hfma2(mh[3], h3, a2);
            float2 fa = __half22float2(a2);
            acc = fmaf(wb[t], fa.x + fa.y, acc);
        }
        out[(d * DIM + hb + r) * DIM + w] = acc;
        vmin = fminf(vmin, acc);
        vmax = fmaxf(vmax, acc);
        vcur = vnext;
    }

    #pragma unroll
    for (int off = 16; off > 0; off >>= 1) {
        vmin = fminf(vmin, __shfl_xor_sync(0xFFFFFFFFu, vmin, off));
        vmax = fmaxf(vmax, __shfl_xor_sync(0xFFFFFFFFu, vmax, off));
    }
    if ((tid & 31) == 0) {
        atomicMin(&g_minmax[0], fenc(vmin));
        atomicMax(&g_minmax[1], fenc(vmax));
    }

    // ---- software grid barrier (all 512 blocks co-resident by construction)
    __syncthreads();                // all threads' STG/atomics issued
    __threadfence();                // visible device-wide
    if (tid == 0) {
        atomicAdd(&g_barrier, 1u);
        while (*(volatile unsigned*)&g_barrier < (unsigned)K3BLOCKS)
            __nanosleep(64);
    }
    __syncthreads();
    __threadfence();                // acquire side

    // ---- fused normalization of this block's own out slice (16 KB, L2-hot)
    float mn = fdec(*(volatile unsigned*)&g_minmax[0]);
    float mx = fdec(*(volatile unsigned*)&g_minmax[1]);
    float inv = 1.0f / (mx - mn + 1e-10f);

    float4* o4 = (float4*)(out + (d * DIM + hb) * DIM);
    float4 v[4];
    #pragma unroll
    for (int q = 0; q < 4; q++) v[q] = o4[tid + q * 256];
    #pragma unroll
    for (int q = 0; q < 4; q++) {
        float4 rr;
        rr.x = (v[q].x - mn) * inv;
        rr.y = (v[q].y - mn) * inv;
        rr.z = (v[q].z - mn) * inv;
        rr.w = (v[q].w - mn) * inv;
        o4[tid + q * 256] = rr;
    }
}

// ---------------------------------------------------------------- launch
extern "C" void kernel_launch(void* const* d_in, const int* in_sizes, int n_in,
                              void* d_out, int out_size) {
    const float* x = (const float*)d_in[0];
    float* out = (float*)d_out;

    k1_hist<<<NT + 1, K1T>>>(x);
    k2_P<<<(DIM * NB * G * G) / 256, 256>>>();
    k3_final<<<dim3(DIM / HROWS, DIM), 256>>>(x, out);
}